// round 14
// baseline (speedup 1.0000x reference)
#include <cuda_runtime.h>
#include <cstdint>

// Problem shapes (fixed by setup_inputs)
#define B      4
#define NC     1024
#define NF     8192

#define TILE   128          // cols per CTA
#define STAGE  512          // rows staged per barrier pair
#define TPB    256          // 16x16 threads
#define ROWSPLIT 4          // CTAs splitting the row dimension
#define NRED   32           // reduction CTAs

#define PADW   18           // sPart row pad

// dynamic smem layout
#define OFF_XY   0
#define OFF_ZW   (STAGE * 16)                        // 8192
#define OFF_PART (OFF_ZW + STAGE * 16)               // 16384
#define OFF_COL  (OFF_PART + STAGE * PADW * 4)       // 53248
#define SMEM_TOTAL (OFF_COL + TILE * 4)              // 53760

typedef unsigned long long u64;

// Scratch (allocation-free rule: __device__ globals).
// Min tracked as atomicMax of ~bits(d): zero is the identity; reduce_kernel
// re-arms slots to 0 after reading -> no init kernel, graph-replay safe.
__device__ unsigned int g_max1[B * NF];   // rows: ret_fine -> nearest gt
__device__ unsigned int g_max2[B * NF];   // cols: gt -> nearest ret_fine
__device__ float        g_part[NRED * 2];
__device__ unsigned int g_done;

// ---- packed f32x2 helpers (sm_103a) ---------------------------------------
__device__ __forceinline__ u64 pk(float lo, float hi) {
    u64 r; asm("mov.b64 %0, {%1, %2};" : "=l"(r) : "f"(lo), "f"(hi)); return r;
}
__device__ __forceinline__ void upk(float& lo, float& hi, u64 v) {
    asm("mov.b64 {%0, %1}, %2;" : "=f"(lo), "=f"(hi) : "l"(v));
}
__device__ __forceinline__ u64 fma2(u64 a, u64 b, u64 c) {
    u64 d; asm("fma.rn.f32x2 %0, %1, %2, %3;" : "=l"(d) : "l"(a), "l"(b), "l"(c)); return d;
}
__device__ __forceinline__ u64 add2(u64 a, u64 b) {
    u64 d; asm("add.rn.f32x2 %0, %1, %2;" : "=l"(d) : "l"(a), "l"(b)); return d;
}

// ---------------------------------------------------------------------------
// Fused pairwise-distance + dual min-reduction.
// Rows staged PRE-PACKED as broadcast f32x2 pairs: inner loop reads two
// LDS.128 and issues zero packing MOVs.
__global__ __launch_bounds__(TPB, 4) void chamfer_kernel(const float* __restrict__ X,
                                                         const float* __restrict__ Y) {
    extern __shared__ unsigned char dyn[];
    ulonglong2*   sXY  = (ulonglong2*)(dyn + OFF_XY);   // {pk(x,x), pk(y,y)}
    ulonglong2*   sZW  = (ulonglong2*)(dyn + OFF_ZW);   // {pk(z,z), pk(w,w)}
    float (*sPart)[PADW] = (float(*)[PADW])(dyn + OFF_PART);
    unsigned int* sCol = (unsigned int*)(dyn + OFF_COL);

    const int tid = threadIdx.x;
    const int tx  = tid & 15;              // 16 col-thread groups (8 cols each)
    const int ty  = tid >> 4;              // 16 row-thread groups
    const int b   = blockIdx.z;
    const int colbase = blockIdx.x * TILE;
    const int row0    = blockIdx.y * (NF / ROWSPLIT);
    const int nStages = (NF / ROWSPLIT) / STAGE;   // 4

    // Stage Y tile through sPart storage: (-2x, -2y, -2z, |y|^2)
    float4* stage = (float4*)sPart;
    if (tid < TILE) {
        int jg = b * NF + colbase + tid;
        float y0 = Y[jg * 3 + 0];
        float y1 = Y[jg * 3 + 1];
        float y2 = Y[jg * 3 + 2];
        stage[tid] = make_float4(-2.0f * y0, -2.0f * y1, -2.0f * y2,
                                 fmaf(y0, y0, fmaf(y1, y1, y2 * y2)));
        sCol[tid] = 0u;
    }
    __syncthreads();

    // Persistent packed column registers: 8 cols as 4 f32x2 groups
    u64 ya[4], yb[4], yc[4], yw[4];
    float cm[8];
#pragma unroll
    for (int g = 0; g < 4; ++g) {
        float4 p = stage[tx * 8 + 2 * g];
        float4 q = stage[tx * 8 + 2 * g + 1];
        ya[g] = pk(p.x, q.x);
        yb[g] = pk(p.y, q.y);
        yc[g] = pk(p.z, q.z);
        yw[g] = pk(p.w, q.w);
        cm[2 * g]     = __int_as_float(0x7f800000);
        cm[2 * g + 1] = __int_as_float(0x7f800000);
    }
    __syncthreads();   // done staging Y through sPart

    for (int t = 0; t < nStages; ++t) {
        const int r0 = row0 + t * STAGE;
        // all 256 threads stage two rows each, pre-packed for broadcast
#pragma unroll
        for (int s = 0; s < 2; ++s) {
            int rr = s * TPB + tid;
            int ig = b * NF + r0 + rr;
            float x0 = X[ig * 3 + 0];
            float x1 = X[ig * 3 + 1];
            float x2 = X[ig * 3 + 2];
            float w  = fmaf(x0, x0, fmaf(x1, x1, x2 * x2));
            sXY[rr] = make_ulonglong2(pk(x0, x0), pk(x1, x1));
            sZW[rr] = make_ulonglong2(pk(x2, x2), pk(w,  w));
        }
        __syncthreads();   // sync A

#pragma unroll
        for (int h = 0; h < 4; ++h) {
#pragma unroll
            for (int i = 0; i < 8; ++i) {
                const int r = h * 128 + ty * 8 + i;
                const ulonglong2 q1 = sXY[r];   // {x,x},{y,y}  (broadcast LDS.128)
                const ulonglong2 q2 = sZW[r];   // {z,z},{w,w}
                float rml = __int_as_float(0x7f800000);
                float rmh = __int_as_float(0x7f800000);
#pragma unroll
                for (int g = 0; g < 4; ++g) {
                    // d = |x|^2 + |y|^2 - 2 x.y  (y pre-scaled by -2, |y|^2 folded)
                    u64 e = add2(yw[g], q2.y);
                    e = fma2(yc[g], q2.x, e);
                    e = fma2(yb[g], q1.y, e);
                    e = fma2(ya[g], q1.x, e);
                    float dl, dh;
                    upk(dl, dh, e);
                    rml = fminf(rml, dl);
                    rmh = fminf(rmh, dh);
                    cm[2 * g]     = fminf(cm[2 * g],     dl);
                    cm[2 * g + 1] = fminf(cm[2 * g + 1], dh);
                }
                sPart[r][tx] = fminf(rml, rmh);
            }
        }
        __syncthreads();   // sync B

        // row fold: two rows per thread (independent chains -> ILP)
#pragma unroll
        for (int s = 0; s < 2; ++s) {
            int rr = s * TPB + tid;
            float m = sPart[rr][0];
#pragma unroll
            for (int c = 1; c < 16; ++c) m = fminf(m, sPart[rr][c]);
            atomicMax(&g_max1[b * NF + r0 + rr],
                      ~__float_as_uint(fmaxf(m, 0.0f)));
        }
        // loop-top sync A orders sPart rewrite after these reads
    }

    // Flush column mins once per CTA
#pragma unroll
    for (int j = 0; j < 8; ++j)
        atomicMax(&sCol[tx * 8 + j], ~__float_as_uint(fmaxf(cm[j], 0.0f)));
    __syncthreads();
    if (tid < TILE)
        atomicMax(&g_max2[b * NF + colbase + tid], sCol[tid]);
}

// ---------------------------------------------------------------------------
// Lean reduce: vectorized loads, warp-shuffle trees, single barrier per block,
// re-arms scratch to 0; last block combines and writes outputs.
__global__ __launch_bounds__(TPB) void reduce_kernel(const float* __restrict__ rc,
                                                     const float* __restrict__ gc,
                                                     float* __restrict__ out) {
    __shared__ float sW[2][8];
    __shared__ bool  sLast;
    const int tid  = threadIdx.x;
    const int lane = tid & 31;
    const int wid  = tid >> 5;
    const int g    = blockIdx.x * TPB + tid;       // [0, 8192)

    uint4 a = ((const uint4*)g_max1)[g];
    uint4 c = ((const uint4*)g_max2)[g];
    ((uint4*)g_max1)[g] = make_uint4(0u, 0u, 0u, 0u);
    ((uint4*)g_max2)[g] = make_uint4(0u, 0u, 0u, 0u);
    float sf = sqrtf(__uint_as_float(~a.x)) + sqrtf(__uint_as_float(~a.y))
             + sqrtf(__uint_as_float(~a.z)) + sqrtf(__uint_as_float(~a.w))
             + sqrtf(__uint_as_float(~c.x)) + sqrtf(__uint_as_float(~c.y))
             + sqrtf(__uint_as_float(~c.z)) + sqrtf(__uint_as_float(~c.w));

    float sc = 0.0f;
    if (g < B * NC) {
        float d0 = rc[g * 3 + 0] - gc[g * 3 + 0];
        float d1 = rc[g * 3 + 1] - gc[g * 3 + 1];
        float d2 = rc[g * 3 + 2] - gc[g * 3 + 2];
        sc = sqrtf(fmaf(d0, d0, fmaf(d1, d1, d2 * d2)));
    }

#pragma unroll
    for (int off = 16; off; off >>= 1) {
        sf += __shfl_xor_sync(0xffffffffu, sf, off);
        sc += __shfl_xor_sync(0xffffffffu, sc, off);
    }
    if (lane == 0) { sW[0][wid] = sf; sW[1][wid] = sc; }
    __syncthreads();
    if (wid == 0) {
        float vf = sW[0][lane & 7];
        float vc = sW[1][lane & 7];
#pragma unroll
        for (int off = 4; off; off >>= 1) {
            vf += __shfl_xor_sync(0xffffffffu, vf, off);
            vc += __shfl_xor_sync(0xffffffffu, vc, off);
        }
        if (lane == 0) {
            g_part[blockIdx.x * 2 + 0] = vf;
            g_part[blockIdx.x * 2 + 1] = vc;
        }
    }

    __threadfence();
    if (tid == 0) sLast = (atomicAdd(&g_done, 1u) == gridDim.x - 1);
    __syncthreads();
    if (!sLast) return;

    if (wid == 0) {
        float vf = g_part[lane * 2 + 0];
        float vc = g_part[lane * 2 + 1];
#pragma unroll
        for (int off = 16; off; off >>= 1) {
            vf += __shfl_xor_sync(0xffffffffu, vf, off);
            vc += __shfl_xor_sync(0xffffffffu, vc, off);
        }
        if (lane == 0) {
            out[0] = vc / (float)(B * NC);              // loss_coarse
            out[1] = vf / (float)(2 * B * NF);          // loss_fine = 0.5*(m1+m2)
            g_done = 0;                                 // reset for next replay
        }
    }
}

// ---------------------------------------------------------------------------
extern "C" void kernel_launch(void* const* d_in, const int* in_sizes, int n_in,
                              void* d_out, int out_size) {
    const float* ret_coarse = (const float*)d_in[0];
    const float* ret_fine   = (const float*)d_in[1];
    const float* gt_fine    = (const float*)d_in[2];
    const float* gt_coarse  = (const float*)d_in[3];
    float* out = (float*)d_out;

    // Idempotent attribute set (host-side, capture-safe, no allocation).
    cudaFuncSetAttribute(chamfer_kernel,
                         cudaFuncAttributeMaxDynamicSharedMemorySize, SMEM_TOTAL);

    dim3 grid(NF / TILE, ROWSPLIT, B);   // (64, 4, 4) = 1024 CTAs
    chamfer_kernel<<<grid, TPB, SMEM_TOTAL>>>(ret_fine, gt_fine);
    reduce_kernel<<<NRED, TPB>>>(ret_coarse, gt_coarse, out);
}

// round 15
// speedup vs baseline: 1.1130x; 1.1130x over previous
#include <cuda_runtime.h>
#include <cstdint>

// Problem shapes (fixed by setup_inputs)
#define B      4
#define NC     1024
#define NF     8192

#define TILE   128          // cols per CTA
#define STAGE  512          // rows staged per barrier pair
#define TPB    256          // 16x16 threads
#define ROWSPLIT 4          // CTAs splitting the row dimension
#define NRED   32           // reduction CTAs (32*256 threads = 8192 = B*NF/4 uint4 slots)

#define PADW   18           // sPart row pad: conflict-free STS

typedef unsigned long long u64;

// Scratch (allocation-free rule: __device__ globals).
// Min tracked as atomicMax of ~bits(d): for d >= 0 the uint bits are monotone,
// so max of complements == complement of min. Zero (module-load init) is the
// identity, and reduce_kernel re-arms slots to 0 after reading -> no init
// kernel needed, graph-replay safe, exact, deterministic.
__device__ unsigned int g_max1[B * NF];   // rows: ret_fine -> nearest gt
__device__ unsigned int g_max2[B * NF];   // cols: gt -> nearest ret_fine
__device__ float        g_part[NRED * 2]; // per-CTA partials {s_fine, s_coarse}
__device__ unsigned int g_done;           // self-resetting

// ---- packed f32x2 helpers (sm_103a) ---------------------------------------
__device__ __forceinline__ u64 pk(float lo, float hi) {
    u64 r; asm("mov.b64 %0, {%1, %2};" : "=l"(r) : "f"(lo), "f"(hi)); return r;
}
__device__ __forceinline__ void upk(float& lo, float& hi, u64 v) {
    asm("mov.b64 {%0, %1}, %2;" : "=f"(lo), "=f"(hi) : "l"(v));
}
__device__ __forceinline__ u64 fma2(u64 a, u64 b, u64 c) {
    u64 d; asm("fma.rn.f32x2 %0, %1, %2, %3;" : "=l"(d) : "l"(a), "l"(b), "l"(c)); return d;
}
__device__ __forceinline__ u64 add2(u64 a, u64 b) {
    u64 d; asm("add.rn.f32x2 %0, %1, %2;" : "=l"(d) : "l"(a), "l"(b)); return d;
}

// ---------------------------------------------------------------------------
// Fused pairwise-distance + dual min-reduction (R13 structure, unchanged).
// grid: (NF/TILE, ROWSPLIT, B), block 16x16, micro-tile 8x8 (cols packed 2-wide).
// 512 rows staged per barrier pair.
__global__ __launch_bounds__(TPB, 4) void chamfer_kernel(const float* __restrict__ X,
                                                         const float* __restrict__ Y) {
    __shared__ float4       sX[STAGE];          // staged rows (x,y,z,|x|^2); Y staging 1st
    __shared__ float        sPart[STAGE][PADW]; // per-(row, tx) partial row mins
    __shared__ unsigned int sCol[TILE];         // CTA col "max of ~bits"

    const int tid = threadIdx.x;
    const int tx  = tid & 15;              // 16 col-thread groups (8 cols each)
    const int ty  = tid >> 4;              // 16 row-thread groups
    const int b   = blockIdx.z;
    const int colbase = blockIdx.x * TILE;
    const int row0    = blockIdx.y * (NF / ROWSPLIT);
    const int nStages = (NF / ROWSPLIT) / STAGE;   // 4

    // Stage Y tile through sX: (-2x, -2y, -2z, |y|^2)
    if (tid < TILE) {
        int jg = b * NF + colbase + tid;
        float y0 = Y[jg * 3 + 0];
        float y1 = Y[jg * 3 + 1];
        float y2 = Y[jg * 3 + 2];
        sX[tid]  = make_float4(-2.0f * y0, -2.0f * y1, -2.0f * y2,
                               fmaf(y0, y0, fmaf(y1, y1, y2 * y2)));
        sCol[tid] = 0u;
    }
    __syncthreads();

    // Persistent packed column registers: 8 cols as 4 f32x2 groups
    u64 ya[4], yb[4], yc[4], yw[4];
    float cm[8];
#pragma unroll
    for (int g = 0; g < 4; ++g) {
        float4 p = sX[tx * 8 + 2 * g];
        float4 q = sX[tx * 8 + 2 * g + 1];
        ya[g] = pk(p.x, q.x);
        yb[g] = pk(p.y, q.y);
        yc[g] = pk(p.z, q.z);
        yw[g] = pk(p.w, q.w);
        cm[2 * g]     = __int_as_float(0x7f800000);
        cm[2 * g + 1] = __int_as_float(0x7f800000);
    }
    __syncthreads();   // done staging Y through sX

    for (int t = 0; t < nStages; ++t) {
        const int r0 = row0 + t * STAGE;
        // all 256 threads stage two rows each
#pragma unroll
        for (int s = 0; s < 2; ++s) {
            int rr = s * TPB + tid;
            int ig = b * NF + r0 + rr;
            float x0 = X[ig * 3 + 0];
            float x1 = X[ig * 3 + 1];
            float x2 = X[ig * 3 + 2];
            sX[rr]  = make_float4(x0, x1, x2, fmaf(x0, x0, fmaf(x1, x1, x2 * x2)));
        }
        __syncthreads();   // sync A

#pragma unroll
        for (int h = 0; h < 4; ++h) {
#pragma unroll
            for (int i = 0; i < 8; ++i) {
                const int r = h * 128 + ty * 8 + i;
                const float4 xp = sX[r];
                const u64 bx = pk(xp.x, xp.x);
                const u64 by = pk(xp.y, xp.y);
                const u64 bz = pk(xp.z, xp.z);
                const u64 bw = pk(xp.w, xp.w);
                float rml = __int_as_float(0x7f800000);
                float rmh = __int_as_float(0x7f800000);
#pragma unroll
                for (int g = 0; g < 4; ++g) {
                    // d = |x|^2 + |y|^2 - 2 x.y  (y pre-scaled by -2, |y|^2 folded)
                    u64 e = add2(yw[g], bw);
                    e = fma2(yc[g], bz, e);
                    e = fma2(yb[g], by, e);
                    e = fma2(ya[g], bx, e);
                    float dl, dh;
                    upk(dl, dh, e);
                    rml = fminf(rml, dl);
                    rmh = fminf(rmh, dh);
                    cm[2 * g]     = fminf(cm[2 * g],     dl);
                    cm[2 * g + 1] = fminf(cm[2 * g + 1], dh);
                }
                sPart[r][tx] = fminf(rml, rmh);
            }
        }
        __syncthreads();   // sync B

        // row fold: two rows per thread (independent chains -> ILP)
#pragma unroll
        for (int s = 0; s < 2; ++s) {
            int rr = s * TPB + tid;
            float m = sPart[rr][0];
#pragma unroll
            for (int c = 1; c < 16; ++c) m = fminf(m, sPart[rr][c]);
            atomicMax(&g_max1[b * NF + r0 + rr],
                      ~__float_as_uint(fmaxf(m, 0.0f)));
        }
        // loop-top sync A orders sPart rewrite after these reads
    }

    // Flush column mins once per CTA
#pragma unroll
    for (int j = 0; j < 8; ++j)
        atomicMax(&sCol[tx * 8 + j], ~__float_as_uint(fmaxf(cm[j], 0.0f)));
    __syncthreads();
    if (tid < TILE)
        atomicMax(&g_max2[b * NF + colbase + tid], sCol[tid]);
}

// ---------------------------------------------------------------------------
// Lean reduce with PDL overlap: the coarse term is independent of chamfer, so
// it runs BEFORE cudaGridDependencySynchronize(); only the fine-term loads
// wait for chamfer completion. Re-arms scratch; last block writes outputs.
__global__ __launch_bounds__(TPB) void reduce_kernel(const float* __restrict__ rc,
                                                     const float* __restrict__ gc,
                                                     float* __restrict__ out) {
    __shared__ float sW[2][8];
    __shared__ bool  sLast;
    const int tid  = threadIdx.x;
    const int lane = tid & 31;
    const int wid  = tid >> 5;
    const int g    = blockIdx.x * TPB + tid;       // [0, 8192)

    // ---- phase 1 (independent of chamfer): coarse term ---------------------
    float sc = 0.0f;
    if (g < B * NC) {
        float d0 = rc[g * 3 + 0] - gc[g * 3 + 0];
        float d1 = rc[g * 3 + 1] - gc[g * 3 + 1];
        float d2 = rc[g * 3 + 2] - gc[g * 3 + 2];
        sc = sqrtf(fmaf(d0, d0, fmaf(d1, d1, d2 * d2)));
    }

    // ---- wait for chamfer's memory to be visible ----------------------------
    cudaGridDependencySynchronize();

    // ---- phase 2: fine term (one uint4 per array, coalesced), re-arm to 0 --
    uint4 a = ((const uint4*)g_max1)[g];
    uint4 c = ((const uint4*)g_max2)[g];
    ((uint4*)g_max1)[g] = make_uint4(0u, 0u, 0u, 0u);
    ((uint4*)g_max2)[g] = make_uint4(0u, 0u, 0u, 0u);
    float sf = sqrtf(__uint_as_float(~a.x)) + sqrtf(__uint_as_float(~a.y))
             + sqrtf(__uint_as_float(~a.z)) + sqrtf(__uint_as_float(~a.w))
             + sqrtf(__uint_as_float(~c.x)) + sqrtf(__uint_as_float(~c.y))
             + sqrtf(__uint_as_float(~c.z)) + sqrtf(__uint_as_float(~c.w));

    // warp tree
#pragma unroll
    for (int off = 16; off; off >>= 1) {
        sf += __shfl_xor_sync(0xffffffffu, sf, off);
        sc += __shfl_xor_sync(0xffffffffu, sc, off);
    }
    if (lane == 0) { sW[0][wid] = sf; sW[1][wid] = sc; }
    __syncthreads();
    if (wid == 0) {
        float vf = sW[0][lane & 7];
        float vc = sW[1][lane & 7];
#pragma unroll
        for (int off = 4; off; off >>= 1) {      // reduce 8 values in lanes 0..7
            vf += __shfl_xor_sync(0xffffffffu, vf, off);
            vc += __shfl_xor_sync(0xffffffffu, vc, off);
        }
        if (lane == 0) {
            g_part[blockIdx.x * 2 + 0] = vf;
            g_part[blockIdx.x * 2 + 1] = vc;
        }
    }

    __threadfence();
    if (tid == 0) sLast = (atomicAdd(&g_done, 1u) == gridDim.x - 1);
    __syncthreads();
    if (!sLast) return;

    // last block: 32 partials per quantity, one warp
    if (wid == 0) {
        float vf = g_part[lane * 2 + 0];
        float vc = g_part[lane * 2 + 1];
#pragma unroll
        for (int off = 16; off; off >>= 1) {
            vf += __shfl_xor_sync(0xffffffffu, vf, off);
            vc += __shfl_xor_sync(0xffffffffu, vc, off);
        }
        if (lane == 0) {
            out[0] = vc / (float)(B * NC);              // loss_coarse
            out[1] = vf / (float)(2 * B * NF);          // loss_fine = 0.5*(m1+m2)
            g_done = 0;                                 // reset for next replay
        }
    }
}

// ---------------------------------------------------------------------------
extern "C" void kernel_launch(void* const* d_in, const int* in_sizes, int n_in,
                              void* d_out, int out_size) {
    const float* ret_coarse = (const float*)d_in[0];
    const float* ret_fine   = (const float*)d_in[1];
    const float* gt_fine    = (const float*)d_in[2];
    const float* gt_coarse  = (const float*)d_in[3];
    float* out = (float*)d_out;

    dim3 grid(NF / TILE, ROWSPLIT, B);   // (64, 4, 4) = 1024 CTAs
    chamfer_kernel<<<grid, TPB>>>(ret_fine, gt_fine);

    // Programmatic dependent launch: reduce overlaps chamfer's drain; its
    // dependent reads are guarded by cudaGridDependencySynchronize().
    cudaLaunchAttribute attrs[1];
    attrs[0].id = cudaLaunchAttributeProgrammaticStreamSerialization;
    attrs[0].val.programmaticStreamSerializationAllowed = 1;
    cudaLaunchConfig_t cfg = {};
    cfg.gridDim  = dim3(NRED, 1, 1);
    cfg.blockDim = dim3(TPB, 1, 1);
    cfg.dynamicSmemBytes = 0;
    cfg.stream = 0;            // same (captured) stream as chamfer
    cfg.attrs = attrs;
    cfg.numAttrs = 1;
    cudaLaunchKernelEx(&cfg, reduce_kernel, ret_coarse, gt_coarse, out);
}

// round 16
// speedup vs baseline: 1.1756x; 1.0562x over previous
#include <cuda_runtime.h>
#include <cstdint>

// Problem shapes (fixed by setup_inputs)
#define B      4
#define NC     1024
#define NF     8192

#define TILE   128          // cols per CTA
#define STAGE  512          // rows staged per barrier pair
#define TPB    256          // 16x16 threads
#define ROWSPLIT 4          // CTAs splitting the row dimension
#define NRED   32           // reduction CTAs (32*256 threads = 8192 = B*NF/4 uint4 slots)

#define PADW   18           // sPart row pad: conflict-free STS

typedef unsigned long long u64;

// Scratch (allocation-free rule: __device__ globals).
// Min tracked as atomicMax of ~bits(d): for d >= 0 the uint bits are monotone,
// so max of complements == complement of min. Zero (module-load init) is the
// identity, and reduce_kernel re-arms slots to 0 after reading -> no init
// kernel needed, graph-replay safe, exact, deterministic.
__device__ unsigned int g_max1[B * NF];   // rows: ret_fine -> nearest gt
__device__ unsigned int g_max2[B * NF];   // cols: gt -> nearest ret_fine
__device__ float        g_part[NRED * 2]; // per-CTA partials {s_fine, s_coarse}
__device__ unsigned int g_done;           // self-resetting

// ---- packed f32x2 helpers (sm_103a) ---------------------------------------
__device__ __forceinline__ u64 pk(float lo, float hi) {
    u64 r; asm("mov.b64 %0, {%1, %2};" : "=l"(r) : "f"(lo), "f"(hi)); return r;
}
__device__ __forceinline__ void upk(float& lo, float& hi, u64 v) {
    asm("mov.b64 {%0, %1}, %2;" : "=f"(lo), "=f"(hi) : "l"(v));
}
__device__ __forceinline__ u64 fma2(u64 a, u64 b, u64 c) {
    u64 d; asm("fma.rn.f32x2 %0, %1, %2, %3;" : "=l"(d) : "l"(a), "l"(b), "l"(c)); return d;
}
__device__ __forceinline__ u64 add2(u64 a, u64 b) {
    u64 d; asm("add.rn.f32x2 %0, %1, %2;" : "=l"(d) : "l"(a), "l"(b)); return d;
}

// ---------------------------------------------------------------------------
// Fused pairwise-distance + dual min-reduction (R13 structure; row-min chains
// restructured into a balanced tree for shorter critical path).
// grid: (NF/TILE, ROWSPLIT, B), block 16x16, micro-tile 8x8 (cols packed 2-wide).
__global__ __launch_bounds__(TPB, 4) void chamfer_kernel(const float* __restrict__ X,
                                                         const float* __restrict__ Y) {
    __shared__ float4       sX[STAGE];          // staged rows (x,y,z,|x|^2); Y staging 1st
    __shared__ float        sPart[STAGE][PADW]; // per-(row, tx) partial row mins
    __shared__ unsigned int sCol[TILE];         // CTA col "max of ~bits"

    const int tid = threadIdx.x;
    const int tx  = tid & 15;              // 16 col-thread groups (8 cols each)
    const int ty  = tid >> 4;              // 16 row-thread groups
    const int b   = blockIdx.z;
    const int colbase = blockIdx.x * TILE;
    const int row0    = blockIdx.y * (NF / ROWSPLIT);
    const int nStages = (NF / ROWSPLIT) / STAGE;   // 4

    // Stage Y tile through sX: (-2x, -2y, -2z, |y|^2)
    if (tid < TILE) {
        int jg = b * NF + colbase + tid;
        float y0 = Y[jg * 3 + 0];
        float y1 = Y[jg * 3 + 1];
        float y2 = Y[jg * 3 + 2];
        sX[tid]  = make_float4(-2.0f * y0, -2.0f * y1, -2.0f * y2,
                               fmaf(y0, y0, fmaf(y1, y1, y2 * y2)));
        sCol[tid] = 0u;
    }
    __syncthreads();

    // Persistent packed column registers: 8 cols as 4 f32x2 groups
    u64 ya[4], yb[4], yc[4], yw[4];
    float cm[8];
#pragma unroll
    for (int g = 0; g < 4; ++g) {
        float4 p = sX[tx * 8 + 2 * g];
        float4 q = sX[tx * 8 + 2 * g + 1];
        ya[g] = pk(p.x, q.x);
        yb[g] = pk(p.y, q.y);
        yc[g] = pk(p.z, q.z);
        yw[g] = pk(p.w, q.w);
        cm[2 * g]     = __int_as_float(0x7f800000);
        cm[2 * g + 1] = __int_as_float(0x7f800000);
    }
    __syncthreads();   // done staging Y through sX

    for (int t = 0; t < nStages; ++t) {
        const int r0 = row0 + t * STAGE;
        // all 256 threads stage two rows each
#pragma unroll
        for (int s = 0; s < 2; ++s) {
            int rr = s * TPB + tid;
            int ig = b * NF + r0 + rr;
            float x0 = X[ig * 3 + 0];
            float x1 = X[ig * 3 + 1];
            float x2 = X[ig * 3 + 2];
            sX[rr]  = make_float4(x0, x1, x2, fmaf(x0, x0, fmaf(x1, x1, x2 * x2)));
        }
        __syncthreads();   // sync A

#pragma unroll
        for (int h = 0; h < 4; ++h) {
#pragma unroll
            for (int i = 0; i < 8; ++i) {
                const int r = h * 128 + ty * 8 + i;
                const float4 xp = sX[r];
                const u64 bx = pk(xp.x, xp.x);
                const u64 by = pk(xp.y, xp.y);
                const u64 bz = pk(xp.z, xp.z);
                const u64 bw = pk(xp.w, xp.w);
                float md[4];
#pragma unroll
                for (int g = 0; g < 4; ++g) {
                    // d = |x|^2 + |y|^2 - 2 x.y  (y pre-scaled by -2, |y|^2 folded)
                    u64 e = add2(yw[g], bw);
                    e = fma2(yc[g], bz, e);
                    e = fma2(yb[g], by, e);
                    e = fma2(ya[g], bx, e);
                    float dl, dh;
                    upk(dl, dh, e);
                    md[g] = fminf(dl, dh);             // independent per-g
                    cm[2 * g]     = fminf(cm[2 * g],     dl);
                    cm[2 * g + 1] = fminf(cm[2 * g + 1], dh);
                }
                // balanced tree merge: depth 2, not an 8-deep serial chain
                sPart[r][tx] = fminf(fminf(md[0], md[1]), fminf(md[2], md[3]));
            }
        }
        __syncthreads();   // sync B

        // row fold: two rows per thread (independent chains -> ILP)
#pragma unroll
        for (int s = 0; s < 2; ++s) {
            int rr = s * TPB + tid;
            float m = sPart[rr][0];
#pragma unroll
            for (int c = 1; c < 16; ++c) m = fminf(m, sPart[rr][c]);
            atomicMax(&g_max1[b * NF + r0 + rr],
                      ~__float_as_uint(fmaxf(m, 0.0f)));
        }
        // loop-top sync A orders sPart rewrite after these reads
    }

    // Flush column mins once per CTA
#pragma unroll
    for (int j = 0; j < 8; ++j)
        atomicMax(&sCol[tx * 8 + j], ~__float_as_uint(fmaxf(cm[j], 0.0f)));
    __syncthreads();
    if (tid < TILE)
        atomicMax(&g_max2[b * NF + colbase + tid], sCol[tid]);
}

// ---------------------------------------------------------------------------
// Lean reduce: vectorized loads, warp-shuffle trees, single barrier per block,
// re-arms scratch to 0; last block combines and writes outputs.
__global__ __launch_bounds__(TPB) void reduce_kernel(const float* __restrict__ rc,
                                                     const float* __restrict__ gc,
                                                     float* __restrict__ out) {
    __shared__ float sW[2][8];
    __shared__ bool  sLast;
    const int tid  = threadIdx.x;
    const int lane = tid & 31;
    const int wid  = tid >> 5;
    const int g    = blockIdx.x * TPB + tid;       // [0, 8192)

    // fine term: one uint4 from each min array (coalesced), re-arm to 0
    uint4 a = ((const uint4*)g_max1)[g];
    uint4 c = ((const uint4*)g_max2)[g];
    ((uint4*)g_max1)[g] = make_uint4(0u, 0u, 0u, 0u);
    ((uint4*)g_max2)[g] = make_uint4(0u, 0u, 0u, 0u);
    float sf = sqrtf(__uint_as_float(~a.x)) + sqrtf(__uint_as_float(~a.y))
             + sqrtf(__uint_as_float(~a.z)) + sqrtf(__uint_as_float(~a.w))
             + sqrtf(__uint_as_float(~c.x)) + sqrtf(__uint_as_float(~c.y))
             + sqrtf(__uint_as_float(~c.z)) + sqrtf(__uint_as_float(~c.w));

    // coarse term: 4096 points over 8192 threads
    float sc = 0.0f;
    if (g < B * NC) {
        float d0 = rc[g * 3 + 0] - gc[g * 3 + 0];
        float d1 = rc[g * 3 + 1] - gc[g * 3 + 1];
        float d2 = rc[g * 3 + 2] - gc[g * 3 + 2];
        sc = sqrtf(fmaf(d0, d0, fmaf(d1, d1, d2 * d2)));
    }

    // warp tree
#pragma unroll
    for (int off = 16; off; off >>= 1) {
        sf += __shfl_xor_sync(0xffffffffu, sf, off);
        sc += __shfl_xor_sync(0xffffffffu, sc, off);
    }
    if (lane == 0) { sW[0][wid] = sf; sW[1][wid] = sc; }
    __syncthreads();
    if (wid == 0) {
        float vf = sW[0][lane & 7];
        float vc = sW[1][lane & 7];
#pragma unroll
        for (int off = 4; off; off >>= 1) {      // reduce 8 values in lanes 0..7
            vf += __shfl_xor_sync(0xffffffffu, vf, off);
            vc += __shfl_xor_sync(0xffffffffu, vc, off);
        }
        if (lane == 0) {
            g_part[blockIdx.x * 2 + 0] = vf;
            g_part[blockIdx.x * 2 + 1] = vc;
        }
    }

    __threadfence();
    if (tid == 0) sLast = (atomicAdd(&g_done, 1u) == gridDim.x - 1);
    __syncthreads();
    if (!sLast) return;

    // last block: 32 partials per quantity, one warp
    if (wid == 0) {
        float vf = g_part[lane * 2 + 0];
        float vc = g_part[lane * 2 + 1];
#pragma unroll
        for (int off = 16; off; off >>= 1) {
            vf += __shfl_xor_sync(0xffffffffu, vf, off);
            vc += __shfl_xor_sync(0xffffffffu, vc, off);
        }
        if (lane == 0) {
            out[0] = vc / (float)(B * NC);              // loss_coarse
            out[1] = vf / (float)(2 * B * NF);          // loss_fine = 0.5*(m1+m2)
            g_done = 0;                                 // reset for next replay
        }
    }
}

// ---------------------------------------------------------------------------
extern "C" void kernel_launch(void* const* d_in, const int* in_sizes, int n_in,
                              void* d_out, int out_size) {
    const float* ret_coarse = (const float*)d_in[0];
    const float* ret_fine   = (const float*)d_in[1];
    const float* gt_fine    = (const float*)d_in[2];
    const float* gt_coarse  = (const float*)d_in[3];
    float* out = (float*)d_out;

    dim3 grid(NF / TILE, ROWSPLIT, B);   // (64, 4, 4) = 1024 CTAs
    chamfer_kernel<<<grid, TPB>>>(ret_fine, gt_fine);
    reduce_kernel<<<NRED, TPB>>>(ret_coarse, gt_coarse, out);
}